// round 14
// baseline (speedup 1.0000x reference)
#include <cuda_runtime.h>

// SSIM loss, (32,1,512,512) fp32. Single fused kernel, vertical-first FIR.
// R12 = R11 + phase-1 load balance: item = (column, 16-output half-ring,
//       26 reads). 276 items / 128 threads = 2.16 balanced rounds, replacing
//       R11's 138/128 split whose round 2 ran a full 42-row ring on 10
//       threads. Loads/output 1.31 -> 1.63 (accepted; L1 was at 32%).
//       FMA count and per-output tap order unchanged (bit-identical).

#define IMG   512
#define TW    128
#define TH    32
#define VC    138         // staged cols (TW + 10)
#define PIT   139         // 139 mod 32 = 11 (f32), mod 16 = 11 (u64): conflict-free
#define NT    128
#define SEGO  16          // outputs per phase-1 item
#define SEGR  26          // rows read per item (SEGO + 10)
#define GX    4
#define GY    16
#define GZ    32
#define NBLK  (GX * GY * GZ)   // 2048

__device__ float        g_partials[NBLK];
__device__ unsigned int g_count;     // zero-init; self-resets

// normalized 1D Gaussian, K=11, sigma=1.5
#define W0 0.00102838f
#define W1 0.00759876f
#define W2 0.03600077f
#define W3 0.10936060f
#define W4 0.21300553f
#define W5 0.26601172f

#define FMA2(d, a, b, c) \
    asm("fma.rn.f32x2 %0, %1, %2, %3;" : "=l"(d) : "l"(a), "l"(b), "l"(c))
#define MUL2(d, a, b) \
    asm("mul.rn.f32x2 %0, %1, %2;" : "=l"(d) : "l"(a), "l"(b))
#define UNPK(lo, hi, v) \
    asm("mov.b64 {%0, %1}, %2;" : "=f"(lo), "=f"(hi) : "l"(v))
#define PK(v, lo, hi) \
    asm("mov.b64 %0, {%1, %2};" : "=l"(v) : "f"(lo), "f"(hi))

__device__ __forceinline__ unsigned long long pk2(float w) {
    unsigned long long r;
    asm("mov.b64 %0, {%1, %1};" : "=l"(r) : "f"(w));
    return r;
}

__global__ __launch_bounds__(NT, 4)
void ssim_fused_kernel(const float* __restrict__ X, const float* __restrict__ Y,
                       float* __restrict__ out)
{
    __shared__ unsigned long long vxy[TH][PIT];  // packed v-conv (x,y) 35.6KB
    __shared__ float              vp [TH][PIT];  // v-conv of x*y       17.8KB
    __shared__ float              wsum[4];
    __shared__ int                s_last;

    const float WGs[11] = {W0, W1, W2, W3, W4, W5, W4, W3, W2, W1, W0};
    const unsigned long long p0 = pk2(W0), p1 = pk2(W1), p2 = pk2(W2),
                             p3 = pk2(W3), p4 = pk2(W4), p5 = pk2(W5);
    const unsigned long long WP[11] = {p0,p1,p2,p3,p4,p5,p4,p3,p2,p1,p0};

    const int tid  = threadIdx.x;
    const int img  = blockIdx.z;
    const int row0 = blockIdx.y * TH - 5;
    const int col0 = blockIdx.x * TW - 5;

    const float* __restrict__ Xi = X + (size_t)img * IMG * IMG;
    const float* __restrict__ Yi = Y + (size_t)img * IMG * IMG;

    const bool rowsafe = (row0 >= 0) && (row0 + TH + 9 < IMG);

    // ---- phase 1: streaming vertical FIR, 16-output half-rings ----
    // item = (column c, segment s of 2); reads 26 rows, writes 16 outputs.
    #pragma unroll 1
    for (int i = tid; i < VC * 2; i += NT) {
        const int c   = (i < VC) ? i : (i - VC);
        const int seg = (i < VC) ? 0 : 1;
        const int gc  = col0 + c;
        const int rb  = row0 + seg * SEGO;
        const int ob  = seg * SEGO;

        if ((unsigned)gc < (unsigned)IMG) {
            const float* __restrict__ px = Xi + gc;
            const float* __restrict__ py = Yi + gc;

            unsigned long long axy[11];
            float ap[11];

            #pragma unroll
            for (int m = 0; m < SEGR; m++) {
                const int gr = rb + m;
                const bool rok = rowsafe || ((unsigned)gr < (unsigned)IMG);
                float xv = rok ? __ldg(px + gr * IMG) : 0.0f;
                float yv = rok ? __ldg(py + gr * IMG) : 0.0f;
                unsigned long long v;
                PK(v, xv, yv);
                float pm = xv * yv;

                #pragma unroll
                for (int o = 0; o < SEGO; o++) {
                    if (o <= m && m <= o + 10) {
                        const int k = m - o;
                        if (k == 0) {             // first tap: init
                            MUL2(axy[o % 11], v, WP[0]);
                            ap[o % 11] = WGs[0] * pm;
                        } else {
                            FMA2(axy[o % 11], v, WP[k], axy[o % 11]);
                            ap[o % 11] = fmaf(WGs[k], pm, ap[o % 11]);
                        }
                    }
                }
                if (m >= 10) {                    // output o = m-10 complete
                    const int o = m - 10;
                    vxy[ob + o][c] = axy[o % 11];
                    vp [ob + o][c] = ap [o % 11];
                }
            }
        } else {
            #pragma unroll
            for (int o = 0; o < SEGO; o++) { vxy[ob + o][c] = 0ull; vp[ob + o][c] = 0.0f; }
        }
    }
    __syncthreads();

    // ---- phase 2: horizontal FIR from smem + SSIM: 512 items, 4 rounds ----
    // item = (row r of 32, colgroup o of 16); 8 outputs, reads 18 cols.
    const float C1 = 0.0001f, C2 = 0.0009f;
    float lsum = 0.0f;
    #pragma unroll 1
    for (int i = tid; i < TH * (TW / 8); i += NT) {
        const int r  = i & 31;
        const int c0 = (i >> 5) * 8;

        unsigned long long acc2[8];
        float accp[8];
        #pragma unroll
        for (int j = 0; j < 8; j++) { acc2[j] = 0ull; accp[j] = 0.0f; }

        #pragma unroll
        for (int m = 0; m < 18; m++) {
            unsigned long long v = vxy[r][c0 + m];   // LDS.64 feeds FMA2 directly
            float pm = vp[r][c0 + m];
            #pragma unroll
            for (int j = 0; j < 8; j++) {
                const int k = m - j;
                if (k >= 0 && k <= 10) {
                    FMA2(acc2[j], v, WP[k], acc2[j]);
                    accp[j] = fmaf(WGs[k], pm, accp[j]);
                }
            }
        }
        #pragma unroll
        for (int j = 0; j < 8; j++) {
            float mu1, mu2;
            UNPK(mu1, mu2, acc2[j]);
            float m12 = mu1 * mu2;
            float sig = accp[j] - m12;
            float sq  = mu1 * mu1 + mu2 * mu2;
            float num = (2.0f * m12 + C1) * (2.0f * sig + C2);
            float den = (sq + C1) * (sq + C2);
            lsum += __fdividef(num, den);
        }
    }

    // ---------------- block reduction (128 threads, 4 warps) ----------------
    #pragma unroll
    for (int off = 16; off > 0; off >>= 1)
        lsum += __shfl_xor_sync(0xFFFFFFFFu, lsum, off);
    if ((tid & 31) == 0) wsum[tid >> 5] = lsum;
    __syncthreads();
    if (tid == 0) {
        float v = wsum[0] + wsum[1] + wsum[2] + wsum[3];
        int bid = blockIdx.x + GX * (blockIdx.y + GY * blockIdx.z);
        g_partials[bid] = v;
        __threadfence();
        unsigned int ticket = atomicAdd(&g_count, 1u);
        s_last = (ticket == NBLK - 1);
    }
    __syncthreads();

    // ---------------- last block: final reduction ----------------
    if (s_last) {
        float s = 0.0f;
        #pragma unroll 4
        for (int i = tid; i < NBLK; i += NT)
            s += *((volatile float*)&g_partials[i]);
        #pragma unroll
        for (int off = 16; off > 0; off >>= 1)
            s += __shfl_xor_sync(0xFFFFFFFFu, s, off);
        __syncthreads();
        if ((tid & 31) == 0) wsum[tid >> 5] = s;
        __syncthreads();
        if (tid == 0) {
            out[0]  = (wsum[0] + wsum[1] + wsum[2] + wsum[3]) * (1.0f / 8388608.0f);
            g_count = 0;
        }
    }
}

extern "C" void kernel_launch(void* const* d_in, const int* in_sizes, int n_in,
                              void* d_out, int out_size)
{
    (void)in_sizes; (void)n_in; (void)out_size;
    const float* X_gt   = (const float*)d_in[0];
    const float* X_pred = (const float*)d_in[1];
    float* out = (float*)d_out;

    dim3 grid(GX, GY, GZ);
    ssim_fused_kernel<<<grid, NT>>>(X_gt, X_pred, out);
}

// round 15
// speedup vs baseline: 1.0534x; 1.0534x over previous
#include <cuda_runtime.h>

// SSIM loss, (32,1,512,512) fp32. Single fused kernel, vertical-first FIR.
// R13 = R11 + straggler fix: phase-1 round 1 is exactly 128 full-ring columns
//       (unchanged hot path); the 10 leftover halo columns run as 40 short
//       quarter-segments (8 outputs, 18 reads) on threads 0-39. Phase-1
//       critical path 1.85 -> ~1.43 round-equivalents. R12's approach
//       (splitting ALL columns) regressed: it taxed the main path +24% loads.

#define IMG   512
#define TW    128
#define TH    32
#define VC    138         // staged cols (TW + 10)
#define PIT   139         // 139 mod 32 = 11 (f32), mod 16 = 11 (u64): conflict-free
#define NT    128
#define NREM  (VC - NT)   // 10 leftover columns
#define GX    4
#define GY    16
#define GZ    32
#define NBLK  (GX * GY * GZ)   // 2048

__device__ float        g_partials[NBLK];
__device__ unsigned int g_count;     // zero-init; self-resets

// normalized 1D Gaussian, K=11, sigma=1.5
#define W0 0.00102838f
#define W1 0.00759876f
#define W2 0.03600077f
#define W3 0.10936060f
#define W4 0.21300553f
#define W5 0.26601172f

#define FMA2(d, a, b, c) \
    asm("fma.rn.f32x2 %0, %1, %2, %3;" : "=l"(d) : "l"(a), "l"(b), "l"(c))
#define MUL2(d, a, b) \
    asm("mul.rn.f32x2 %0, %1, %2;" : "=l"(d) : "l"(a), "l"(b))
#define UNPK(lo, hi, v) \
    asm("mov.b64 {%0, %1}, %2;" : "=f"(lo), "=f"(hi) : "l"(v))
#define PK(v, lo, hi) \
    asm("mov.b64 %0, {%1, %2};" : "=l"(v) : "f"(lo), "f"(hi))

__device__ __forceinline__ unsigned long long pk2(float w) {
    unsigned long long r;
    asm("mov.b64 %0, {%1, %1};" : "=l"(r) : "f"(w));
    return r;
}

__global__ __launch_bounds__(NT, 4)
void ssim_fused_kernel(const float* __restrict__ X, const float* __restrict__ Y,
                       float* __restrict__ out)
{
    __shared__ unsigned long long vxy[TH][PIT];  // packed v-conv (x,y) 35.6KB
    __shared__ float              vp [TH][PIT];  // v-conv of x*y       17.8KB
    __shared__ float              wsum[4];
    __shared__ int                s_last;

    const float WGs[11] = {W0, W1, W2, W3, W4, W5, W4, W3, W2, W1, W0};
    const unsigned long long p0 = pk2(W0), p1 = pk2(W1), p2 = pk2(W2),
                             p3 = pk2(W3), p4 = pk2(W4), p5 = pk2(W5);
    const unsigned long long WP[11] = {p0,p1,p2,p3,p4,p5,p4,p3,p2,p1,p0};

    const int tid  = threadIdx.x;
    const int img  = blockIdx.z;
    const int row0 = blockIdx.y * TH - 5;
    const int col0 = blockIdx.x * TW - 5;

    const float* __restrict__ Xi = X + (size_t)img * IMG * IMG;
    const float* __restrict__ Yi = Y + (size_t)img * IMG * IMG;

    const bool rowsafe = (row0 >= 0) && (row0 + TH + 9 < IMG);

    // ---- phase 1a: full-ring FIR on columns 0..127 (one balanced round) ----
    {
        const int c  = tid;
        const int gc = col0 + c;
        if ((unsigned)gc < (unsigned)IMG) {
            const float* __restrict__ px = Xi + gc;
            const float* __restrict__ py = Yi + gc;

            unsigned long long axy[11];
            float ap[11];

            #pragma unroll
            for (int m = 0; m < TH + 10; m++) {
                const int gr = row0 + m;
                const bool rok = rowsafe || ((unsigned)gr < (unsigned)IMG);
                float xv = rok ? __ldg(px + gr * IMG) : 0.0f;
                float yv = rok ? __ldg(py + gr * IMG) : 0.0f;
                unsigned long long v;
                PK(v, xv, yv);
                float pm = xv * yv;

                #pragma unroll
                for (int o = 0; o < TH; o++) {
                    if (o <= m && m <= o + 10) {
                        const int k = m - o;
                        if (k == 0) {
                            MUL2(axy[o % 11], v, WP[0]);
                            ap[o % 11] = WGs[0] * pm;
                        } else {
                            FMA2(axy[o % 11], v, WP[k], axy[o % 11]);
                            ap[o % 11] = fmaf(WGs[k], pm, ap[o % 11]);
                        }
                    }
                }
                if (m >= 10) {
                    const int o = m - 10;
                    vxy[o][c] = axy[o % 11];
                    vp [o][c] = ap [o % 11];
                }
            }
        } else {
            #pragma unroll
            for (int o = 0; o < TH; o++) { vxy[o][c] = 0ull; vp[o][c] = 0.0f; }
        }
    }

    // ---- phase 1b: 10 leftover columns as 40 quarter-segments (8 out, 18 reads) ----
    if (tid < NREM * 4) {
        const int c   = NT + (tid % NREM);      // columns 128..137
        const int seg = tid / NREM;             // 0..3
        const int gc  = col0 + c;
        const int rb  = row0 + seg * 8;
        const int ob  = seg * 8;

        if ((unsigned)gc < (unsigned)IMG) {
            const float* __restrict__ px = Xi + gc;
            const float* __restrict__ py = Yi + gc;

            unsigned long long axy[8];
            float ap[8];

            #pragma unroll
            for (int m = 0; m < 18; m++) {
                const int gr = rb + m;
                const bool rok = rowsafe || ((unsigned)gr < (unsigned)IMG);
                float xv = rok ? __ldg(px + gr * IMG) : 0.0f;
                float yv = rok ? __ldg(py + gr * IMG) : 0.0f;
                unsigned long long v;
                PK(v, xv, yv);
                float pm = xv * yv;

                #pragma unroll
                for (int o = 0; o < 8; o++) {
                    if (o <= m && m <= o + 10) {
                        const int k = m - o;
                        if (k == 0) {
                            MUL2(axy[o], v, WP[0]);
                            ap[o] = WGs[0] * pm;
                        } else {
                            FMA2(axy[o], v, WP[k], axy[o]);
                            ap[o] = fmaf(WGs[k], pm, ap[o]);
                        }
                    }
                }
                if (m >= 10) {
                    const int o = m - 10;
                    vxy[ob + o][c] = axy[o];
                    vp [ob + o][c] = ap[o];
                }
            }
        } else {
            #pragma unroll
            for (int o = 0; o < 8; o++) { vxy[ob + o][c] = 0ull; vp[ob + o][c] = 0.0f; }
        }
    }
    __syncthreads();

    // ---- phase 2: horizontal FIR from smem + SSIM: 512 items, 4 rounds ----
    const float C1 = 0.0001f, C2 = 0.0009f;
    float lsum = 0.0f;
    #pragma unroll 1
    for (int i = tid; i < TH * (TW / 8); i += NT) {
        const int r  = i & 31;
        const int c0 = (i >> 5) * 8;

        unsigned long long acc2[8];
        float accp[8];
        #pragma unroll
        for (int j = 0; j < 8; j++) { acc2[j] = 0ull; accp[j] = 0.0f; }

        #pragma unroll
        for (int m = 0; m < 18; m++) {
            unsigned long long v = vxy[r][c0 + m];   // LDS.64 feeds FMA2 directly
            float pm = vp[r][c0 + m];
            #pragma unroll
            for (int j = 0; j < 8; j++) {
                const int k = m - j;
                if (k >= 0 && k <= 10) {
                    FMA2(acc2[j], v, WP[k], acc2[j]);
                    accp[j] = fmaf(WGs[k], pm, accp[j]);
                }
            }
        }
        #pragma unroll
        for (int j = 0; j < 8; j++) {
            float mu1, mu2;
            UNPK(mu1, mu2, acc2[j]);
            float m12 = mu1 * mu2;
            float sig = accp[j] - m12;
            float sq  = mu1 * mu1 + mu2 * mu2;
            float num = (2.0f * m12 + C1) * (2.0f * sig + C2);
            float den = (sq + C1) * (sq + C2);
            lsum += __fdividef(num, den);
        }
    }

    // ---------------- block reduction (128 threads, 4 warps) ----------------
    #pragma unroll
    for (int off = 16; off > 0; off >>= 1)
        lsum += __shfl_xor_sync(0xFFFFFFFFu, lsum, off);
    if ((tid & 31) == 0) wsum[tid >> 5] = lsum;
    __syncthreads();
    if (tid == 0) {
        float v = wsum[0] + wsum[1] + wsum[2] + wsum[3];
        int bid = blockIdx.x + GX * (blockIdx.y + GY * blockIdx.z);
        g_partials[bid] = v;
        __threadfence();
        unsigned int ticket = atomicAdd(&g_count, 1u);
        s_last = (ticket == NBLK - 1);
    }
    __syncthreads();

    // ---------------- last block: final reduction ----------------
    if (s_last) {
        float s = 0.0f;
        #pragma unroll 4
        for (int i = tid; i < NBLK; i += NT)
            s += *((volatile float*)&g_partials[i]);
        #pragma unroll
        for (int off = 16; off > 0; off >>= 1)
            s += __shfl_xor_sync(0xFFFFFFFFu, s, off);
        __syncthreads();
        if ((tid & 31) == 0) wsum[tid >> 5] = s;
        __syncthreads();
        if (tid == 0) {
            out[0]  = (wsum[0] + wsum[1] + wsum[2] + wsum[3]) * (1.0f / 8388608.0f);
            g_count = 0;
        }
    }
}

extern "C" void kernel_launch(void* const* d_in, const int* in_sizes, int n_in,
                              void* d_out, int out_size)
{
    (void)in_sizes; (void)n_in; (void)out_size;
    const float* X_gt   = (const float*)d_in[0];
    const float* X_pred = (const float*)d_in[1];
    float* out = (float*)d_out;

    dim3 grid(GX, GY, GZ);
    ssim_fused_kernel<<<grid, NT>>>(X_gt, X_pred, out);
}